// round 10
// baseline (speedup 1.0000x reference)
#include <cuda_runtime.h>
#include <cstdint>

#define N_NODES 250000
#define N_EDGES 4000000
#define NODE_F  4
#define HID     32
#define NN      50
#define NF      3
#define D_IN    9
#define OUT_C   53
#define TILES   (N_EDGES / 32)   // 125000 warp-tiles
#define EBLOCKS 592              // persistent edge blocks (148 SMs * 4)

// Scratch (device globals)
__device__ float  g_accC[N_NODES];                 // 1 MB
__device__ __align__(8) float2 g_accMS[N_NODES];   // 2 MB (tail nodes only)
__device__ float g_conc[N_NODES];
__device__ float g_S;
__device__ int   g_ei_is64;
__device__ float g_sc, g_sm, g_ss;                 // b2 . W*[4:36]
__device__ float g_uc[HID], g_um[HID], g_us[HID];  // W2 @ W*[4:36]
__device__ unsigned g_W1t[16 * HID];               // tf32 W1 padded to K=16 (row 9 = b1)

__device__ __forceinline__ float softplusf(float x) {
    return fmaxf(x, 0.0f) + log1pf(expf(-fabsf(x)));
}
__device__ __forceinline__ unsigned f2tf32(float f) {
    unsigned u; asm("cvt.rna.tf32.f32 %0, %1;" : "=r"(u) : "f"(f)); return u;
}
__device__ __forceinline__ void mma_tf32(float d[4],
                                         unsigned a0, unsigned a1, unsigned a2, unsigned a3,
                                         unsigned b0, unsigned b1) {
    asm("mma.sync.aligned.m16n8k8.row.col.f32.tf32.tf32.f32 "
        "{%0,%1,%2,%3}, {%4,%5,%6,%7}, {%8,%9}, {%0,%1,%2,%3};"
        : "+f"(d[0]), "+f"(d[1]), "+f"(d[2]), "+f"(d[3])
        : "r"(a0), "r"(a1), "r"(a2), "r"(a3), "r"(b0), "r"(b1));
}

// ---------------------------------------------------------------------------
// Launch 1: prep (dtype detect, projections, tf32 W1) — 1 warp
// ---------------------------------------------------------------------------
__global__ void prep_kernel(const int* __restrict__ ei32,
                            const float* __restrict__ W1,
                            const float* __restrict__ b1,
                            const float* __restrict__ W2,
                            const float* __restrict__ b2,
                            const float* __restrict__ Wc,
                            const float* __restrict__ Wmu,
                            const float* __restrict__ Wsig)
{
    const int k = threadIdx.x;
    if (k == 0) {
        int z = 0;
        #pragma unroll
        for (int i = 1; i < 64; i += 2) z |= ei32[i];
        g_ei_is64 = (z == 0) ? 1 : 0;
        g_S = 0.0f;
    }
    float uc = 0.f, um = 0.f, us = 0.f;
    #pragma unroll
    for (int m = 0; m < HID; m++) {
        const float w = W2[k * HID + m];
        uc = fmaf(w, Wc[NODE_F + m],   uc);
        um = fmaf(w, Wmu[NODE_F + m],  um);
        us = fmaf(w, Wsig[NODE_F + m], us);
    }
    g_uc[k] = uc; g_um[k] = um; g_us[k] = us;

    #pragma unroll
    for (int d = 0; d < D_IN; d++) g_W1t[d * HID + k] = f2tf32(W1[d * HID + k]);
    g_W1t[9 * HID + k] = f2tf32(b1[k]);
    #pragma unroll
    for (int d = 10; d < 16; d++) g_W1t[d * HID + k] = 0u;

    float pc = b2[k] * Wc[NODE_F + k];
    float pm = b2[k] * Wmu[NODE_F + k];
    float ps = b2[k] * Wsig[NODE_F + k];
    #pragma unroll
    for (int off = 16; off > 0; off >>= 1) {
        pc += __shfl_xor_sync(0xffffffffu, pc, off);
        pm += __shfl_xor_sync(0xffffffffu, pm, off);
        ps += __shfl_xor_sync(0xffffffffu, ps, off);
    }
    if (k == 0) { g_sc = pc; g_sm = pm; g_ss = ps; }
}

// ---------------------------------------------------------------------------
// Launch 2 / 3: zero accC, zero accMS (split so edge lands at launch slot 4)
// ---------------------------------------------------------------------------
__global__ void zeroC_kernel() {
    const int i = blockIdx.x * blockDim.x + threadIdx.x;
    if (i < N_NODES) g_accC[i] = 0.0f;
}
__global__ void zeroMS_kernel() {
    const int i = blockIdx.x * blockDim.x + threadIdx.x;
    if (i < N_NODES && i % NN >= NN - NF) g_accMS[i] = make_float2(0.f, 0.f);
}

// ---------------------------------------------------------------------------
// Launch 4: persistent tensor-core edge MLP with 1-deep software pipeline.
// ---------------------------------------------------------------------------
#define ROWW 20   // padded SMEM row stride in words (80 B, conflict-free)

__global__ __launch_bounds__(256, 4) void edge_kernel(
    const float* __restrict__ x,
    const void* __restrict__ ei_raw,
    const float* __restrict__ ea)
{
    __shared__ unsigned sA[8 * 32 * ROWW];         // 20 KB staging
    __shared__ float suc[HID], sum_[HID], sus[HID];

    const int tid  = threadIdx.x;
    const int warp = tid >> 5;
    const int lane = tid & 31;
    const int grp  = lane >> 2;   // 0..7
    const int tig  = lane & 3;    // 0..3

    if (tid < HID) {
        suc[tid]  = g_uc[tid];
        sum_[tid] = g_um[tid];
        sus[tid]  = g_us[tid];
    }

    // B fragments for H = A[32x16] @ W1t[16x32], loaded once per CTA
    unsigned B0[2][4], B1[2][4];
    #pragma unroll
    for (int kt = 0; kt < 2; kt++)
        #pragma unroll
        for (int nt = 0; nt < 4; nt++) {
            B0[kt][nt] = g_W1t[(kt * 8 + tig)     * HID + nt * 8 + grp];
            B1[kt][nt] = g_W1t[(kt * 8 + tig + 4) * HID + nt * 8 + grp];
        }
    __syncthreads();

    const int is64 = g_ei_is64;
    const int GS   = EBLOCKS * 8;                  // 4736 warps in flight
    const int gw   = blockIdx.x * 8 + warp;
    const float4* x4 = reinterpret_cast<const float4*>(x);
    const float sc = g_sc, sm = g_sm, ss = g_ss;
    unsigned* aw = &sA[warp * 32 * ROWW];

    // ---- pipeline prologue: load tile gw ----
    int r0, c0; float av0; float4 xr0, xc0;
    {
        const int e = gw * 32 + lane;
        if (is64) {
            const long long* ei = (const long long*)ei_raw;
            r0 = (int)__ldg(ei + e); c0 = (int)__ldg(ei + N_EDGES + e);
        } else {
            const int* ei = (const int*)ei_raw;
            r0 = __ldg(ei + e); c0 = __ldg(ei + N_EDGES + e);
        }
        av0 = __ldg(ea + e);
        xr0 = __ldg(x4 + r0); xc0 = __ldg(x4 + c0);
    }

    for (int t = gw; t < TILES; t += GS) {
        // ---- prefetch tile t+GS (idx chain + gathers) while computing t ----
        int r1 = 0, c1 = 0; float av1 = 0.f;
        float4 xr1 = make_float4(0,0,0,0), xc1 = make_float4(0,0,0,0);
        const int tn = t + GS;
        if (tn < TILES) {
            const int e = tn * 32 + lane;
            if (is64) {
                const long long* ei = (const long long*)ei_raw;
                r1 = (int)__ldg(ei + e); c1 = (int)__ldg(ei + N_EDGES + e);
            } else {
                const int* ei = (const int*)ei_raw;
                r1 = __ldg(ei + e); c1 = __ldg(ei + N_EDGES + e);
            }
            av1 = __ldg(ea + e);
            xr1 = __ldg(x4 + r1); xc1 = __ldg(x4 + c1);
        }

        // ---- stage current tile ----
        __syncwarp();   // all lanes done reading A-fragments of previous tile
        {
            uint4* row = reinterpret_cast<uint4*>(&aw[lane * ROWW]);
            row[0] = make_uint4(f2tf32(xr0.x), f2tf32(xr0.y), f2tf32(xr0.z), f2tf32(xr0.w));
            row[1] = make_uint4(f2tf32(xc0.x), f2tf32(xc0.y), f2tf32(xc0.z), f2tf32(xc0.w));
            row[2] = make_uint4(f2tf32(av0), 0x3f800000u, 0u, 0u);
            row[3] = make_uint4(0u, 0u, 0u, 0u);
        }
        __syncwarp();

        // ---- MMAs ----
        float D[2][4][4];
        #pragma unroll
        for (int h = 0; h < 2; h++)
            #pragma unroll
            for (int nt = 0; nt < 4; nt++)
                #pragma unroll
                for (int q = 0; q < 4; q++) D[h][nt][q] = 0.0f;

        #pragma unroll
        for (int h = 0; h < 2; h++) {
            #pragma unroll
            for (int kt = 0; kt < 2; kt++) {
                const unsigned a0 = aw[(h * 16 + grp)     * ROWW + kt * 8 + tig];
                const unsigned a1 = aw[(h * 16 + grp + 8) * ROWW + kt * 8 + tig];
                const unsigned a2 = aw[(h * 16 + grp)     * ROWW + kt * 8 + tig + 4];
                const unsigned a3 = aw[(h * 16 + grp + 8) * ROWW + kt * 8 + tig + 4];
                #pragma unroll
                for (int nt = 0; nt < 4; nt++)
                    mma_tf32(D[h][nt], a0, a1, a2, a3, B0[kt][nt], B1[kt][nt]);
            }
        }

        // ---- epilogue: relu + project, quad-reduce, scatter ----
        #pragma unroll
        for (int h = 0; h < 2; h++) {
            float pcA = 0.f, pcB = 0.f, pmA = 0.f, pmB = 0.f, psA = 0.f, psB = 0.f;
            #pragma unroll
            for (int nt = 0; nt < 4; nt++) {
                const int cc = nt * 8 + 2 * tig;
                const float u0 = suc[cc],  u1 = suc[cc + 1];
                const float m0 = sum_[cc], m1 = sum_[cc + 1];
                const float s0 = sus[cc],  s1 = sus[cc + 1];
                const float h0 = fmaxf(D[h][nt][0], 0.f);
                const float h1 = fmaxf(D[h][nt][1], 0.f);
                const float h2 = fmaxf(D[h][nt][2], 0.f);
                const float h3 = fmaxf(D[h][nt][3], 0.f);
                pcA = fmaf(h0, u0, fmaf(h1, u1, pcA));
                pcB = fmaf(h2, u0, fmaf(h3, u1, pcB));
                pmA = fmaf(h0, m0, fmaf(h1, m1, pmA));
                pmB = fmaf(h2, m0, fmaf(h3, m1, pmB));
                psA = fmaf(h0, s0, fmaf(h1, s1, psA));
                psB = fmaf(h2, s0, fmaf(h3, s1, psB));
            }
            #pragma unroll
            for (int off = 1; off <= 2; off <<= 1) {
                pcA += __shfl_xor_sync(0xffffffffu, pcA, off);
                pcB += __shfl_xor_sync(0xffffffffu, pcB, off);
                pmA += __shfl_xor_sync(0xffffffffu, pmA, off);
                pmB += __shfl_xor_sync(0xffffffffu, pmB, off);
                psA += __shfl_xor_sync(0xffffffffu, psA, off);
                psB += __shfl_xor_sync(0xffffffffu, psB, off);
            }
            const int rA = __shfl_sync(0xffffffffu, r0, h * 16 + grp);
            const int rB = __shfl_sync(0xffffffffu, r0, h * 16 + grp + 8);
            if (tig == 0) {
                asm volatile("red.global.add.f32 [%0], %1;"
                             :: "l"(&g_accC[rA]), "f"(pcA + sc) : "memory");
                asm volatile("red.global.add.f32 [%0], %1;"
                             :: "l"(&g_accC[rB]), "f"(pcB + sc) : "memory");
                if (rA % NN >= NN - NF)
                    asm volatile("red.global.add.v2.f32 [%0], {%1, %2};"
                                 :: "l"(&g_accMS[rA]), "f"(pmA + sm), "f"(psA + ss) : "memory");
                if (rB % NN >= NN - NF)
                    asm volatile("red.global.add.v2.f32 [%0], {%1, %2};"
                                 :: "l"(&g_accMS[rB]), "f"(pmB + sm), "f"(psB + ss) : "memory");
            }
        }

        // ---- rotate pipeline ----
        r0 = r1; c0 = c1; av0 = av1; xr0 = xr1; xc0 = xc1;
    }
}

// ---------------------------------------------------------------------------
// Launch 5: per-node heads + conc sum
// ---------------------------------------------------------------------------
__global__ __launch_bounds__(256) void node_kernel(
    const float* __restrict__ x,
    const float* __restrict__ Wc,  const float* __restrict__ bc,
    const float* __restrict__ Wmu, const float* __restrict__ bmu,
    const float* __restrict__ Wsig,const float* __restrict__ bsig,
    const float* __restrict__ high,
    float* __restrict__ out)
{
    __shared__ float sWarp[8];
    const int i = blockIdx.x * blockDim.x + threadIdx.x;

    float concv = 0.0f;
    if (i < N_NODES) {
        const float  ac = g_accC[i];
        const float4 xi = __ldg(reinterpret_cast<const float4*>(x) + i);

        const float craw = xi.x * __ldg(Wc+0) + xi.y * __ldg(Wc+1)
                         + xi.z * __ldg(Wc+2) + xi.w * __ldg(Wc+3)
                         + ac + __ldg(bc) + 1e-10f;
        concv = softplusf(craw);
        g_conc[i] = concv;

        const int p = i % NN;
        if (p >= NN - NF) {
            const float2 ms = g_accMS[i];
            const float mraw = xi.x * __ldg(Wmu+0) + xi.y * __ldg(Wmu+1)
                             + xi.z * __ldg(Wmu+2) + xi.w * __ldg(Wmu+3)
                             + ms.x + __ldg(bmu) + 1e-20f;
            const float sraw = xi.x * __ldg(Wsig+0) + xi.y * __ldg(Wsig+1)
                             + xi.z * __ldg(Wsig+2) + xi.w * __ldg(Wsig+3)
                             + ms.y + __ldg(bsig) + 1e-20f;
            const float alpha = softplusf(mraw) + 1e-20f;
            const float beta  = softplusf(sraw) + 1e-20f;
            const int g = i / NN;
            const int j = p - (NN - NF);
            out[g * OUT_C + NN + j] = alpha / (alpha + beta) * __ldg(high + j);
        }
    }

    float s = concv;
    #pragma unroll
    for (int off = 16; off > 0; off >>= 1) s += __shfl_xor_sync(0xffffffffu, s, off);
    if ((threadIdx.x & 31) == 0) sWarp[threadIdx.x >> 5] = s;
    __syncthreads();
    if (threadIdx.x == 0) {
        float tsum = 0.f;
        #pragma unroll
        for (int w = 0; w < 8; w++) tsum += sWarp[w];
        atomicAdd(&g_S, tsum);
    }
}

// ---------------------------------------------------------------------------
// Launch 6: normalize conc
// ---------------------------------------------------------------------------
__global__ void final_kernel(float* __restrict__ out) {
    const int i = blockIdx.x * blockDim.x + threadIdx.x;
    if (i >= N_NODES) return;
    const float invS = 1.0f / (g_S + 1e-20f);
    out[(i / NN) * OUT_C + (i % NN)] = g_conc[i] * invS;
}

// ---------------------------------------------------------------------------
extern "C" void kernel_launch(void* const* d_in, const int* in_sizes, int n_in,
                              void* d_out, int out_size) {
    const float* x    = (const float*)d_in[0];
    const void*  ei   = d_in[1];
    const float* ea   = (const float*)d_in[2];
    const float* high = (const float*)d_in[3];
    const float* W1   = (const float*)d_in[4];
    const float* b1   = (const float*)d_in[5];
    const float* W2   = (const float*)d_in[6];
    const float* b2   = (const float*)d_in[7];
    const float* Wc   = (const float*)d_in[8];
    const float* bc   = (const float*)d_in[9];
    const float* Wmu  = (const float*)d_in[10];
    const float* bmu  = (const float*)d_in[11];
    const float* Wsig = (const float*)d_in[12];
    const float* bsig = (const float*)d_in[13];
    float* out = (float*)d_out;

    prep_kernel  <<<1, 32>>>((const int*)ei, W1, b1, W2, b2, Wc, Wmu, Wsig);
    zeroC_kernel <<<(N_NODES + 255) / 256, 256>>>();
    zeroMS_kernel<<<(N_NODES + 255) / 256, 256>>>();
    edge_kernel  <<<EBLOCKS, 256>>>(x, ei, ea);
    node_kernel  <<<(N_NODES + 255) / 256, 256>>>(x, Wc, bc, Wmu, bmu, Wsig, bsig, high, out);
    final_kernel <<<(N_NODES + 255) / 256, 256>>>(out);
}

// round 11
// speedup vs baseline: 1.3106x; 1.3106x over previous
#include <cuda_runtime.h>
#include <cstdint>

#define N_NODES 250000
#define N_EDGES 4000000
#define NODE_F  4
#define HID     32
#define NN      50
#define NF      3
#define OUT_C   53
#define ROWW    12    // staging row stride in words (48 B: 16B-aligned, frag reads conflict-free)

// Scratch (device globals)
__device__ float  g_accC[N_NODES];                 // 1 MB
__device__ __align__(8) float2 g_accMS[N_NODES];   // 2 MB (tail nodes only)
__device__ float g_conc[N_NODES];
__device__ float g_S;
__device__ int   g_ei_is64;
__device__ float g_sc, g_sm, g_ss;                 // b2 . W*[4:36]
__device__ unsigned g_W1t[8 * HID];                // tf32 W1 rows 0..7 (the x features)
// Epilogue constants, packed per column-pair p (cols 2p, 2p+1):
__device__ __align__(16) float4 g_epi0[16];        // {uc0, uc1, um0, um1}
__device__ __align__(16) float4 g_epi1[16];        // {us0, us1, w8_0, w8_1}
__device__ __align__(8)  float2 g_epi2[16];        // {b0, b1}

__device__ __forceinline__ float softplusf(float x) {
    return fmaxf(x, 0.0f) + log1pf(expf(-fabsf(x)));
}
__device__ __forceinline__ unsigned f2tf32(float f) {
    unsigned u; asm("cvt.rna.tf32.f32 %0, %1;" : "=r"(u) : "f"(f)); return u;
}
__device__ __forceinline__ void mma_tf32(float d[4],
                                         unsigned a0, unsigned a1, unsigned a2, unsigned a3,
                                         unsigned b0, unsigned b1) {
    asm("mma.sync.aligned.m16n8k8.row.col.f32.tf32.tf32.f32 "
        "{%0,%1,%2,%3}, {%4,%5,%6,%7}, {%8,%9}, {%0,%1,%2,%3};"
        : "+f"(d[0]), "+f"(d[1]), "+f"(d[2]), "+f"(d[3])
        : "r"(a0), "r"(a1), "r"(a2), "r"(a3), "r"(b0), "r"(b1));
}
__device__ __forceinline__ void cp_async16(unsigned dst, const void* src) {
    asm volatile("cp.async.ca.shared.global [%0], [%1], 16;" :: "r"(dst), "l"(src));
}

// ---------------------------------------------------------------------------
// Launch 1: prep — dtype detect, projections, tf32 W1, packed epilogue consts
// ---------------------------------------------------------------------------
__global__ void prep_kernel(const int* __restrict__ ei32,
                            const float* __restrict__ W1,
                            const float* __restrict__ b1,
                            const float* __restrict__ W2,
                            const float* __restrict__ b2,
                            const float* __restrict__ Wc,
                            const float* __restrict__ Wmu,
                            const float* __restrict__ Wsig)
{
    __shared__ float suc[HID], sum_[HID], sus[HID];
    const int k = threadIdx.x;
    if (k == 0) {
        int z = 0;
        #pragma unroll
        for (int i = 1; i < 64; i += 2) z |= ei32[i];
        g_ei_is64 = (z == 0) ? 1 : 0;
        g_S = 0.0f;
    }
    float uc = 0.f, um = 0.f, us = 0.f;
    #pragma unroll
    for (int m = 0; m < HID; m++) {
        const float w = W2[k * HID + m];
        uc = fmaf(w, Wc[NODE_F + m],   uc);
        um = fmaf(w, Wmu[NODE_F + m],  um);
        us = fmaf(w, Wsig[NODE_F + m], us);
    }
    suc[k] = uc; sum_[k] = um; sus[k] = us;

    #pragma unroll
    for (int d = 0; d < 8; d++) g_W1t[d * HID + k] = f2tf32(W1[d * HID + k]);

    __syncwarp();
    if (k < 16) {
        const int c0 = 2 * k, c1 = 2 * k + 1;
        g_epi0[k] = make_float4(suc[c0], suc[c1], sum_[c0], sum_[c1]);
        g_epi1[k] = make_float4(sus[c0], sus[c1], W1[8 * HID + c0], W1[8 * HID + c1]);
        g_epi2[k] = make_float2(b1[c0], b1[c1]);
    }

    float pc = b2[k] * Wc[NODE_F + k];
    float pm = b2[k] * Wmu[NODE_F + k];
    float ps = b2[k] * Wsig[NODE_F + k];
    #pragma unroll
    for (int off = 16; off > 0; off >>= 1) {
        pc += __shfl_xor_sync(0xffffffffu, pc, off);
        pm += __shfl_xor_sync(0xffffffffu, pm, off);
        ps += __shfl_xor_sync(0xffffffffu, ps, off);
    }
    if (k == 0) { g_sc = pc; g_sm = pm; g_ss = ps; }
}

// ---------------------------------------------------------------------------
// Launch 2 / 3: zero accC, zero accMS
// ---------------------------------------------------------------------------
__global__ void zeroC_kernel() {
    const int i = blockIdx.x * blockDim.x + threadIdx.x;
    if (i < N_NODES) g_accC[i] = 0.0f;
}
__global__ void zeroMS_kernel() {
    const int i = blockIdx.x * blockDim.x + threadIdx.x;
    if (i < N_NODES && i % NN >= NN - NF) g_accMS[i] = make_float2(0.f, 0.f);
}

// ---------------------------------------------------------------------------
// Launch 4: edge MLP. Warp = 32 edges; cp.async gathers; K=8 tf32 MMA.
// ---------------------------------------------------------------------------
__global__ __launch_bounds__(256) void edge_kernel(
    const float* __restrict__ x,
    const void* __restrict__ ei_raw,
    const float* __restrict__ ea)
{
    __shared__ __align__(16) float sA[8 * 32 * ROWW];   // 12 KB staging
    __shared__ __align__(16) float4 sE0[16], sE1[16];
    __shared__ __align__(8)  float2 sE2[16];

    const int tid  = threadIdx.x;
    const int warp = tid >> 5;
    const int lane = tid & 31;
    const int grp  = lane >> 2;   // 0..7
    const int tig  = lane & 3;    // 0..3

    if (tid < 16) {
        sE0[tid] = g_epi0[tid];
        sE1[tid] = g_epi1[tid];
        sE2[tid] = g_epi2[tid];
    }

    const int e = (blockIdx.x * 8 + warp) * 32 + lane;

    int r, c;
    if (g_ei_is64) {
        const long long* ei = (const long long*)ei_raw;
        r = (int)__ldg(ei + e);
        c = (int)__ldg(ei + N_EDGES + e);
    } else {
        const int* ei = (const int*)ei_raw;
        r = __ldg(ei + e);
        c = __ldg(ei + N_EDGES + e);
    }
    const float av = __ldg(ea + e);

    // cp.async gathers: x[r] -> row cols 0..3, x[c] -> row cols 4..7
    const unsigned rowAddr = (unsigned)__cvta_generic_to_shared(
        &sA[(warp * 32 + lane) * ROWW]);
    cp_async16(rowAddr,      x + (size_t)r * 4);
    cp_async16(rowAddr + 16, x + (size_t)c * 4);
    asm volatile("cp.async.commit_group;");

    // B fragments (K=8): b0 at (k=tig, n), b1 at (k=tig+4, n)
    unsigned B0[4], B1[4];
    #pragma unroll
    for (int nt = 0; nt < 4; nt++) {
        B0[nt] = g_W1t[tig       * HID + nt * 8 + grp];
        B1[nt] = g_W1t[(tig + 4) * HID + nt * 8 + grp];
    }

    asm volatile("cp.async.wait_group 0;");
    __syncthreads();

    // A fragments from staging (+ tf32 round), then 8 MMAs
    const float* aw = &sA[warp * 32 * ROWW];
    float D[2][4][4];
    #pragma unroll
    for (int h = 0; h < 2; h++) {
        const unsigned a0 = f2tf32(aw[(h * 16 + grp)     * ROWW + tig]);
        const unsigned a1 = f2tf32(aw[(h * 16 + grp + 8) * ROWW + tig]);
        const unsigned a2 = f2tf32(aw[(h * 16 + grp)     * ROWW + tig + 4]);
        const unsigned a3 = f2tf32(aw[(h * 16 + grp + 8) * ROWW + tig + 4]);
        #pragma unroll
        for (int nt = 0; nt < 4; nt++) {
            D[h][nt][0] = D[h][nt][1] = D[h][nt][2] = D[h][nt][3] = 0.0f;
            mma_tf32(D[h][nt], a0, a1, a2, a3, B0[nt], B1[nt]);
        }
    }

    // ea of the rows this lane's fragments belong to
    const float eaA0 = __shfl_sync(0xffffffffu, av, grp);
    const float eaB0 = __shfl_sync(0xffffffffu, av, grp + 8);
    const float eaA1 = __shfl_sync(0xffffffffu, av, grp + 16);
    const float eaB1 = __shfl_sync(0xffffffffu, av, grp + 24);

    // Epilogue: add ea*w8 + b, relu, project, quad-reduce, scatter
    float pcA[2] = {0.f, 0.f}, pcB[2] = {0.f, 0.f};
    float pmA[2] = {0.f, 0.f}, pmB[2] = {0.f, 0.f};
    float psA[2] = {0.f, 0.f}, psB[2] = {0.f, 0.f};

    #pragma unroll
    for (int nt = 0; nt < 4; nt++) {
        const int p = nt * 4 + tig;
        const float4 E0 = sE0[p];   // uc0, uc1, um0, um1
        const float4 E1 = sE1[p];   // us0, us1, w8_0, w8_1
        const float2 E2 = sE2[p];   // b0, b1
        #pragma unroll
        for (int h = 0; h < 2; h++) {
            const float eaA = h ? eaA1 : eaA0;
            const float eaB = h ? eaB1 : eaB0;
            const float h0 = fmaxf(fmaf(eaA, E1.z, D[h][nt][0] + E2.x), 0.f);
            const float h1 = fmaxf(fmaf(eaA, E1.w, D[h][nt][1] + E2.y), 0.f);
            const float h2 = fmaxf(fmaf(eaB, E1.z, D[h][nt][2] + E2.x), 0.f);
            const float h3 = fmaxf(fmaf(eaB, E1.w, D[h][nt][3] + E2.y), 0.f);
            pcA[h] = fmaf(h0, E0.x, fmaf(h1, E0.y, pcA[h]));
            pcB[h] = fmaf(h2, E0.x, fmaf(h3, E0.y, pcB[h]));
            pmA[h] = fmaf(h0, E0.z, fmaf(h1, E0.w, pmA[h]));
            pmB[h] = fmaf(h2, E0.z, fmaf(h3, E0.w, pmB[h]));
            psA[h] = fmaf(h0, E1.x, fmaf(h1, E1.y, psA[h]));
            psB[h] = fmaf(h2, E1.x, fmaf(h3, E1.y, psB[h]));
        }
    }

    const float sc = g_sc, sm = g_sm, ss = g_ss;
    #pragma unroll
    for (int h = 0; h < 2; h++) {
        #pragma unroll
        for (int off = 1; off <= 2; off <<= 1) {
            pcA[h] += __shfl_xor_sync(0xffffffffu, pcA[h], off);
            pcB[h] += __shfl_xor_sync(0xffffffffu, pcB[h], off);
            pmA[h] += __shfl_xor_sync(0xffffffffu, pmA[h], off);
            pmB[h] += __shfl_xor_sync(0xffffffffu, pmB[h], off);
            psA[h] += __shfl_xor_sync(0xffffffffu, psA[h], off);
            psB[h] += __shfl_xor_sync(0xffffffffu, psB[h], off);
        }
        const int rA = __shfl_sync(0xffffffffu, r, h * 16 + grp);
        const int rB = __shfl_sync(0xffffffffu, r, h * 16 + grp + 8);
        if (tig == 0) {
            asm volatile("red.global.add.f32 [%0], %1;"
                         :: "l"(&g_accC[rA]), "f"(pcA[h] + sc) : "memory");
            asm volatile("red.global.add.f32 [%0], %1;"
                         :: "l"(&g_accC[rB]), "f"(pcB[h] + sc) : "memory");
            if (rA % NN >= NN - NF)
                asm volatile("red.global.add.v2.f32 [%0], {%1, %2};"
                             :: "l"(&g_accMS[rA]), "f"(pmA[h] + sm), "f"(psA[h] + ss) : "memory");
            if (rB % NN >= NN - NF)
                asm volatile("red.global.add.v2.f32 [%0], {%1, %2};"
                             :: "l"(&g_accMS[rB]), "f"(pmB[h] + sm), "f"(psB[h] + ss) : "memory");
        }
    }
}

// ---------------------------------------------------------------------------
// Launch 5: per-node heads + conc sum
// ---------------------------------------------------------------------------
__global__ __launch_bounds__(256) void node_kernel(
    const float* __restrict__ x,
    const float* __restrict__ Wc,  const float* __restrict__ bc,
    const float* __restrict__ Wmu, const float* __restrict__ bmu,
    const float* __restrict__ Wsig,const float* __restrict__ bsig,
    const float* __restrict__ high,
    float* __restrict__ out)
{
    __shared__ float sWarp[8];
    const int i = blockIdx.x * blockDim.x + threadIdx.x;

    float concv = 0.0f;
    if (i < N_NODES) {
        const float  ac = g_accC[i];
        const float4 xi = __ldg(reinterpret_cast<const float4*>(x) + i);

        const float craw = xi.x * __ldg(Wc+0) + xi.y * __ldg(Wc+1)
                         + xi.z * __ldg(Wc+2) + xi.w * __ldg(Wc+3)
                         + ac + __ldg(bc) + 1e-10f;
        concv = softplusf(craw);
        g_conc[i] = concv;

        const int p = i % NN;
        if (p >= NN - NF) {
            const float2 ms = g_accMS[i];
            const float mraw = xi.x * __ldg(Wmu+0) + xi.y * __ldg(Wmu+1)
                             + xi.z * __ldg(Wmu+2) + xi.w * __ldg(Wmu+3)
                             + ms.x + __ldg(bmu) + 1e-20f;
            const float sraw = xi.x * __ldg(Wsig+0) + xi.y * __ldg(Wsig+1)
                             + xi.z * __ldg(Wsig+2) + xi.w * __ldg(Wsig+3)
                             + ms.y + __ldg(bsig) + 1e-20f;
            const float alpha = softplusf(mraw) + 1e-20f;
            const float beta  = softplusf(sraw) + 1e-20f;
            const int g = i / NN;
            const int j = p - (NN - NF);
            out[g * OUT_C + NN + j] = alpha / (alpha + beta) * __ldg(high + j);
        }
    }

    float s = concv;
    #pragma unroll
    for (int off = 16; off > 0; off >>= 1) s += __shfl_xor_sync(0xffffffffu, s, off);
    if ((threadIdx.x & 31) == 0) sWarp[threadIdx.x >> 5] = s;
    __syncthreads();
    if (threadIdx.x == 0) {
        float tsum = 0.f;
        #pragma unroll
        for (int w = 0; w < 8; w++) tsum += sWarp[w];
        atomicAdd(&g_S, tsum);
    }
}

// ---------------------------------------------------------------------------
// Launch 6: normalize conc
// ---------------------------------------------------------------------------
__global__ void final_kernel(float* __restrict__ out) {
    const int i = blockIdx.x * blockDim.x + threadIdx.x;
    if (i >= N_NODES) return;
    const float invS = 1.0f / (g_S + 1e-20f);
    out[(i / NN) * OUT_C + (i % NN)] = g_conc[i] * invS;
}

// ---------------------------------------------------------------------------
extern "C" void kernel_launch(void* const* d_in, const int* in_sizes, int n_in,
                              void* d_out, int out_size) {
    const float* x    = (const float*)d_in[0];
    const void*  ei   = d_in[1];
    const float* ea   = (const float*)d_in[2];
    const float* high = (const float*)d_in[3];
    const float* W1   = (const float*)d_in[4];
    const float* b1   = (const float*)d_in[5];
    const float* W2   = (const float*)d_in[6];
    const float* b2   = (const float*)d_in[7];
    const float* Wc   = (const float*)d_in[8];
    const float* bc   = (const float*)d_in[9];
    const float* Wmu  = (const float*)d_in[10];
    const float* bmu  = (const float*)d_in[11];
    const float* Wsig = (const float*)d_in[12];
    const float* bsig = (const float*)d_in[13];
    float* out = (float*)d_out;

    prep_kernel  <<<1, 32>>>((const int*)ei, W1, b1, W2, b2, Wc, Wmu, Wsig);
    zeroC_kernel <<<(N_NODES + 255) / 256, 256>>>();
    zeroMS_kernel<<<(N_NODES + 255) / 256, 256>>>();
    edge_kernel  <<<N_EDGES / (32 * 8), 256>>>(x, ei, ea);   // 15625 blocks
    node_kernel  <<<(N_NODES + 255) / 256, 256>>>(x, Wc, bc, Wmu, bmu, Wsig, bsig, high, out);
    final_kernel <<<(N_NODES + 255) / 256, 256>>>(out);
}

// round 12
// speedup vs baseline: 1.3822x; 1.0546x over previous
#include <cuda_runtime.h>
#include <cstdint>

#define N_NODES 250000
#define N_EDGES 4000000
#define NODE_F  4
#define HID     32
#define NN      50
#define NF      3
#define OUT_C   53
#define ROWW    12    // staging row stride in words (48 B)
#define TILES   (N_EDGES / 32)

// Scratch (device globals)
__device__ float  g_accC[N_NODES];                 // 1 MB
__device__ __align__(8) float2 g_accMS[N_NODES];   // 2 MB (tail nodes only)
__device__ float g_conc[N_NODES];
__device__ float g_S;
__device__ int   g_ei_is64;
__device__ float g_sc, g_sm, g_ss;                 // b2 . W*[4:36]
__device__ unsigned g_W1t[8 * HID];                // tf32 W1 rows 0..7
__device__ __align__(16) float4 g_epi0[16];        // {uc0, uc1, um0, um1} per col-pair
__device__ __align__(16) float4 g_epi1[16];        // {us0, us1, w8_0, w8_1}
__device__ __align__(8)  float2 g_epi2[16];        // {b0, b1}

__device__ __forceinline__ float softplusf(float x) {
    return fmaxf(x, 0.0f) + log1pf(expf(-fabsf(x)));
}
__device__ __forceinline__ unsigned f2tf32(float f) {
    unsigned u; asm("cvt.rna.tf32.f32 %0, %1;" : "=r"(u) : "f"(f)); return u;
}
__device__ __forceinline__ void mma_tf32(float d[4],
                                         unsigned a0, unsigned a1, unsigned a2, unsigned a3,
                                         unsigned b0, unsigned b1) {
    asm("mma.sync.aligned.m16n8k8.row.col.f32.tf32.tf32.f32 "
        "{%0,%1,%2,%3}, {%4,%5,%6,%7}, {%8,%9}, {%0,%1,%2,%3};"
        : "+f"(d[0]), "+f"(d[1]), "+f"(d[2]), "+f"(d[3])
        : "r"(a0), "r"(a1), "r"(a2), "r"(a3), "r"(b0), "r"(b1));
}
__device__ __forceinline__ void cp_async16(unsigned dst, const void* src) {
    asm volatile("cp.async.ca.shared.global [%0], [%1], 16;" :: "r"(dst), "l"(src));
}

// ---------------------------------------------------------------------------
// Launch 1: prep
// ---------------------------------------------------------------------------
__global__ void prep_kernel(const int* __restrict__ ei32,
                            const float* __restrict__ W1,
                            const float* __restrict__ b1,
                            const float* __restrict__ W2,
                            const float* __restrict__ b2,
                            const float* __restrict__ Wc,
                            const float* __restrict__ Wmu,
                            const float* __restrict__ Wsig)
{
    __shared__ float suc[HID], sum_[HID], sus[HID];
    const int k = threadIdx.x;
    if (k == 0) {
        int z = 0;
        #pragma unroll
        for (int i = 1; i < 64; i += 2) z |= ei32[i];
        g_ei_is64 = (z == 0) ? 1 : 0;
        g_S = 0.0f;
    }
    float uc = 0.f, um = 0.f, us = 0.f;
    #pragma unroll
    for (int m = 0; m < HID; m++) {
        const float w = W2[k * HID + m];
        uc = fmaf(w, Wc[NODE_F + m],   uc);
        um = fmaf(w, Wmu[NODE_F + m],  um);
        us = fmaf(w, Wsig[NODE_F + m], us);
    }
    suc[k] = uc; sum_[k] = um; sus[k] = us;

    #pragma unroll
    for (int d = 0; d < 8; d++) g_W1t[d * HID + k] = f2tf32(W1[d * HID + k]);

    __syncwarp();
    if (k < 16) {
        const int c0 = 2 * k, c1 = 2 * k + 1;
        g_epi0[k] = make_float4(suc[c0], suc[c1], sum_[c0], sum_[c1]);
        g_epi1[k] = make_float4(sus[c0], sus[c1], W1[8 * HID + c0], W1[8 * HID + c1]);
        g_epi2[k] = make_float2(b1[c0], b1[c1]);
    }

    float pc = b2[k] * Wc[NODE_F + k];
    float pm = b2[k] * Wmu[NODE_F + k];
    float ps = b2[k] * Wsig[NODE_F + k];
    #pragma unroll
    for (int off = 16; off > 0; off >>= 1) {
        pc += __shfl_xor_sync(0xffffffffu, pc, off);
        pm += __shfl_xor_sync(0xffffffffu, pm, off);
        ps += __shfl_xor_sync(0xffffffffu, ps, off);
    }
    if (k == 0) { g_sc = pc; g_sm = pm; g_ss = ps; }
}

// ---------------------------------------------------------------------------
// Launch 2 / 3: zero accC, zero accMS
// ---------------------------------------------------------------------------
__global__ void zeroC_kernel() {
    const int i = blockIdx.x * blockDim.x + threadIdx.x;
    if (i < N_NODES) g_accC[i] = 0.0f;
}
__global__ void zeroMS_kernel() {
    const int i = blockIdx.x * blockDim.x + threadIdx.x;
    if (i < N_NODES && i % NN >= NN - NF) g_accMS[i] = make_float2(0.f, 0.f);
}

// ---------------------------------------------------------------------------
// Per-tile worker: frags -> MMA -> epilogue -> scatter
// ---------------------------------------------------------------------------
__device__ __forceinline__ void process_tile(
    const float* aw, int r, float av,
    const unsigned B0[4], const unsigned B1[4],
    const float4* sE0, const float4* sE1, const float2* sE2,
    int lane, int grp, int tig, float sc, float sm, float ss)
{
    float D[2][4][4];
    #pragma unroll
    for (int h = 0; h < 2; h++) {
        const unsigned a0 = f2tf32(aw[(h * 16 + grp)     * ROWW + tig]);
        const unsigned a1 = f2tf32(aw[(h * 16 + grp + 8) * ROWW + tig]);
        const unsigned a2 = f2tf32(aw[(h * 16 + grp)     * ROWW + tig + 4]);
        const unsigned a3 = f2tf32(aw[(h * 16 + grp + 8) * ROWW + tig + 4]);
        #pragma unroll
        for (int nt = 0; nt < 4; nt++) {
            D[h][nt][0] = D[h][nt][1] = D[h][nt][2] = D[h][nt][3] = 0.0f;
            mma_tf32(D[h][nt], a0, a1, a2, a3, B0[nt], B1[nt]);
        }
    }

    const float eaA0 = __shfl_sync(0xffffffffu, av, grp);
    const float eaB0 = __shfl_sync(0xffffffffu, av, grp + 8);
    const float eaA1 = __shfl_sync(0xffffffffu, av, grp + 16);
    const float eaB1 = __shfl_sync(0xffffffffu, av, grp + 24);

    float pcA[2] = {0.f, 0.f}, pcB[2] = {0.f, 0.f};
    float pmA[2] = {0.f, 0.f}, pmB[2] = {0.f, 0.f};
    float psA[2] = {0.f, 0.f}, psB[2] = {0.f, 0.f};

    #pragma unroll
    for (int nt = 0; nt < 4; nt++) {
        const int p = nt * 4 + tig;
        const float4 E0 = sE0[p];
        const float4 E1 = sE1[p];
        const float2 E2 = sE2[p];
        #pragma unroll
        for (int h = 0; h < 2; h++) {
            const float eaA = h ? eaA1 : eaA0;
            const float eaB = h ? eaB1 : eaB0;
            const float h0 = fmaxf(fmaf(eaA, E1.z, D[h][nt][0] + E2.x), 0.f);
            const float h1 = fmaxf(fmaf(eaA, E1.w, D[h][nt][1] + E2.y), 0.f);
            const float h2 = fmaxf(fmaf(eaB, E1.z, D[h][nt][2] + E2.x), 0.f);
            const float h3 = fmaxf(fmaf(eaB, E1.w, D[h][nt][3] + E2.y), 0.f);
            pcA[h] = fmaf(h0, E0.x, fmaf(h1, E0.y, pcA[h]));
            pcB[h] = fmaf(h2, E0.x, fmaf(h3, E0.y, pcB[h]));
            pmA[h] = fmaf(h0, E0.z, fmaf(h1, E0.w, pmA[h]));
            pmB[h] = fmaf(h2, E0.z, fmaf(h3, E0.w, pmB[h]));
            psA[h] = fmaf(h0, E1.x, fmaf(h1, E1.y, psA[h]));
            psB[h] = fmaf(h2, E1.x, fmaf(h3, E1.y, psB[h]));
        }
    }

    #pragma unroll
    for (int h = 0; h < 2; h++) {
        #pragma unroll
        for (int off = 1; off <= 2; off <<= 1) {
            pcA[h] += __shfl_xor_sync(0xffffffffu, pcA[h], off);
            pcB[h] += __shfl_xor_sync(0xffffffffu, pcB[h], off);
            pmA[h] += __shfl_xor_sync(0xffffffffu, pmA[h], off);
            pmB[h] += __shfl_xor_sync(0xffffffffu, pmB[h], off);
            psA[h] += __shfl_xor_sync(0xffffffffu, psA[h], off);
            psB[h] += __shfl_xor_sync(0xffffffffu, psB[h], off);
        }
        const int rA = __shfl_sync(0xffffffffu, r, h * 16 + grp);
        const int rB = __shfl_sync(0xffffffffu, r, h * 16 + grp + 8);
        if (tig == 0) {
            asm volatile("red.global.add.f32 [%0], %1;"
                         :: "l"(&g_accC[rA]), "f"(pcA[h] + sc) : "memory");
            asm volatile("red.global.add.f32 [%0], %1;"
                         :: "l"(&g_accC[rB]), "f"(pcB[h] + sc) : "memory");
            if (rA % NN >= NN - NF)
                asm volatile("red.global.add.v2.f32 [%0], {%1, %2};"
                             :: "l"(&g_accMS[rA]), "f"(pmA[h] + sm), "f"(psA[h] + ss) : "memory");
            if (rB % NN >= NN - NF)
                asm volatile("red.global.add.v2.f32 [%0], {%1, %2};"
                             :: "l"(&g_accMS[rB]), "f"(pmB[h] + sm), "f"(psB[h] + ss) : "memory");
        }
    }
}

// ---------------------------------------------------------------------------
// Launch 4: edge MLP — 2 tiles/warp, cp.async pipelined, warp-local sync only
// ---------------------------------------------------------------------------
__global__ __launch_bounds__(256) void edge_kernel(
    const float* __restrict__ x,
    const void* __restrict__ ei_raw,
    const float* __restrict__ ea)
{
    __shared__ __align__(16) float sA[2 * 8 * 32 * ROWW];  // 24 KB staging
    __shared__ __align__(16) float4 sE0[16], sE1[16];
    __shared__ __align__(8)  float2 sE2[16];

    const int tid  = threadIdx.x;
    const int warp = tid >> 5;
    const int lane = tid & 31;
    const int grp  = lane >> 2;
    const int tig  = lane & 3;

    if (tid < 16) {
        sE0[tid] = g_epi0[tid];
        sE1[tid] = g_epi1[tid];
        sE2[tid] = g_epi2[tid];
    }

    const int t0 = (blockIdx.x * 8 + warp) * 2;   // even; t1 = t0+1
    if (t0 >= TILES) { __syncthreads(); return; }

    const int is64 = g_ei_is64;
    float* aw0 = &sA[(warp * 2 + 0) * 32 * ROWW];
    float* aw1 = &sA[(warp * 2 + 1) * 32 * ROWW];

    // ---- issue both tiles' index loads + gathers ----
    int r0, c0, r1, c1;
    {
        const int e0 = t0 * 32 + lane;
        const int e1 = e0 + 32;
        if (is64) {
            const long long* ei = (const long long*)ei_raw;
            r0 = (int)__ldg(ei + e0); c0 = (int)__ldg(ei + N_EDGES + e0);
            r1 = (int)__ldg(ei + e1); c1 = (int)__ldg(ei + N_EDGES + e1);
        } else {
            const int* ei = (const int*)ei_raw;
            r0 = __ldg(ei + e0); c0 = __ldg(ei + N_EDGES + e0);
            r1 = __ldg(ei + e1); c1 = __ldg(ei + N_EDGES + e1);
        }
    }
    const float av0 = __ldg(ea + t0 * 32 + lane);
    const float av1 = __ldg(ea + t0 * 32 + 32 + lane);

    const unsigned a0addr = (unsigned)__cvta_generic_to_shared(&aw0[lane * ROWW]);
    cp_async16(a0addr,      x + (size_t)r0 * 4);
    cp_async16(a0addr + 16, x + (size_t)c0 * 4);
    asm volatile("cp.async.commit_group;");
    const unsigned a1addr = (unsigned)__cvta_generic_to_shared(&aw1[lane * ROWW]);
    cp_async16(a1addr,      x + (size_t)r1 * 4);
    cp_async16(a1addr + 16, x + (size_t)c1 * 4);
    asm volatile("cp.async.commit_group;");

    // B fragments (const-cached, once per warp)
    unsigned B0[4], B1[4];
    #pragma unroll
    for (int nt = 0; nt < 4; nt++) {
        B0[nt] = g_W1t[tig       * HID + nt * 8 + grp];
        B1[nt] = g_W1t[(tig + 4) * HID + nt * 8 + grp];
    }

    const float sc = g_sc, sm = g_sm, ss = g_ss;

    __syncthreads();   // sE visibility; gathers still in flight

    // ---- tile 0 ----
    asm volatile("cp.async.wait_group 1;");
    __syncwarp();
    process_tile(aw0, r0, av0, B0, B1, sE0, sE1, sE2, lane, grp, tig, sc, sm, ss);

    // ---- tile 1 ----
    asm volatile("cp.async.wait_group 0;");
    __syncwarp();
    process_tile(aw1, r1, av1, B0, B1, sE0, sE1, sE2, lane, grp, tig, sc, sm, ss);
}

// ---------------------------------------------------------------------------
// Launch 5: per-node heads + conc sum
// ---------------------------------------------------------------------------
__global__ __launch_bounds__(256) void node_kernel(
    const float* __restrict__ x,
    const float* __restrict__ Wc,  const float* __restrict__ bc,
    const float* __restrict__ Wmu, const float* __restrict__ bmu,
    const float* __restrict__ Wsig,const float* __restrict__ bsig,
    const float* __restrict__ high,
    float* __restrict__ out)
{
    __shared__ float sWarp[8];
    const int i = blockIdx.x * blockDim.x + threadIdx.x;

    float concv = 0.0f;
    if (i < N_NODES) {
        const float  ac = g_accC[i];
        const float4 xi = __ldg(reinterpret_cast<const float4*>(x) + i);

        const float craw = xi.x * __ldg(Wc+0) + xi.y * __ldg(Wc+1)
                         + xi.z * __ldg(Wc+2) + xi.w * __ldg(Wc+3)
                         + ac + __ldg(bc) + 1e-10f;
        concv = softplusf(craw);
        g_conc[i] = concv;

        const int p = i % NN;
        if (p >= NN - NF) {
            const float2 ms = g_accMS[i];
            const float mraw = xi.x * __ldg(Wmu+0) + xi.y * __ldg(Wmu+1)
                             + xi.z * __ldg(Wmu+2) + xi.w * __ldg(Wmu+3)
                             + ms.x + __ldg(bmu) + 1e-20f;
            const float sraw = xi.x * __ldg(Wsig+0) + xi.y * __ldg(Wsig+1)
                             + xi.z * __ldg(Wsig+2) + xi.w * __ldg(Wsig+3)
                             + ms.y + __ldg(bsig) + 1e-20f;
            const float alpha = softplusf(mraw) + 1e-20f;
            const float beta  = softplusf(sraw) + 1e-20f;
            const int g = i / NN;
            const int j = p - (NN - NF);
            out[g * OUT_C + NN + j] = alpha / (alpha + beta) * __ldg(high + j);
        }
    }

    float s = concv;
    #pragma unroll
    for (int off = 16; off > 0; off >>= 1) s += __shfl_xor_sync(0xffffffffu, s, off);
    if ((threadIdx.x & 31) == 0) sWarp[threadIdx.x >> 5] = s;
    __syncthreads();
    if (threadIdx.x == 0) {
        float tsum = 0.f;
        #pragma unroll
        for (int w = 0; w < 8; w++) tsum += sWarp[w];
        atomicAdd(&g_S, tsum);
    }
}

// ---------------------------------------------------------------------------
// Launch 6: normalize conc
// ---------------------------------------------------------------------------
__global__ void final_kernel(float* __restrict__ out) {
    const int i = blockIdx.x * blockDim.x + threadIdx.x;
    if (i >= N_NODES) return;
    const float invS = 1.0f / (g_S + 1e-20f);
    out[(i / NN) * OUT_C + (i % NN)] = g_conc[i] * invS;
}

// ---------------------------------------------------------------------------
extern "C" void kernel_launch(void* const* d_in, const int* in_sizes, int n_in,
                              void* d_out, int out_size) {
    const float* x    = (const float*)d_in[0];
    const void*  ei   = d_in[1];
    const float* ea   = (const float*)d_in[2];
    const float* high = (const float*)d_in[3];
    const float* W1   = (const float*)d_in[4];
    const float* b1   = (const float*)d_in[5];
    const float* W2   = (const float*)d_in[6];
    const float* b2   = (const float*)d_in[7];
    const float* Wc   = (const float*)d_in[8];
    const float* bc   = (const float*)d_in[9];
    const float* Wmu  = (const float*)d_in[10];
    const float* bmu  = (const float*)d_in[11];
    const float* Wsig = (const float*)d_in[12];
    const float* bsig = (const float*)d_in[13];
    float* out = (float*)d_out;

    prep_kernel  <<<1, 32>>>((const int*)ei, W1, b1, W2, b2, Wc, Wmu, Wsig);
    zeroC_kernel <<<(N_NODES + 255) / 256, 256>>>();
    zeroMS_kernel<<<(N_NODES + 255) / 256, 256>>>();
    edge_kernel  <<<(TILES / 2 + 7) / 8, 256>>>(x, ei, ea);   // 7813 blocks
    node_kernel  <<<(N_NODES + 255) / 256, 256>>>(x, Wc, bc, Wmu, bmu, Wsig, bsig, high, out);
    final_kernel <<<(N_NODES + 255) / 256, 256>>>(out);
}